// round 1
// baseline (speedup 1.0000x reference)
#include <cuda_runtime.h>
#include <math_constants.h>

// Problem constants
#define BATCHSZ 4096
#define DIM     256
#define NROWS   8192           // 2 * BATCHSZ
#define SIMSCALE 2.0f          // 1 / temperature (0.5)

// GEMM tiling
#define BM 128
#define BN 128
#define BK 32
#define TM 8
#define TN 8
#define NTHREADS 256
#define NROWTILES (NROWS / BM) // 64
#define NCHUNK 16
#define CHUNK_COLS (NROWS / NCHUNK) // 512
#define LDA (BM + 4)           // +4 pad: 4-way (not 8-way) STS conflicts, keeps 16B alignment

// Scratch (allocation-free rule: __device__ globals)
__device__ float g_pm[NCHUNK][NROWS];   // partial row max per column-chunk
__device__ float g_ps[NCHUNK][NROWS];   // partial row sumexp per column-chunk
__device__ float g_lrow[NROWS];         // per-row loss

__device__ __forceinline__ const float* row_ptr(const float* hi, const float* hj, int r) {
    return (r < BATCHSZ) ? (hi + (size_t)r * DIM) : (hj + (size_t)(r - BATCHSZ) * DIM);
}

// Fused sim-tile GEMM + online logsumexp.
// Block = (row tile rt of 128 rows) x (column chunk ch of 512 cols).
// Thread (tx, ty) with tx = tid%16, ty = tid/16 owns the 8x8 register tile at
// rows r0 + ty*8 + i, cols c0 + tx*8 + j.
__global__ __launch_bounds__(NTHREADS, 1)
void sim_lse_kernel(const float* __restrict__ hi, const float* __restrict__ hj) {
    const int rt = blockIdx.x & (NROWTILES - 1);
    const int ch = blockIdx.x / NROWTILES;
    const int r0 = rt * BM;
    const int cbeg = ch * CHUNK_COLS;

    __shared__ float As[BK][LDA];   // transposed: As[k][m]
    __shared__ float Bs[BK][LDA];   // transposed: Bs[k][n]

    const int tid = threadIdx.x;
    const int tx = tid & 15;
    const int ty = tid >> 4;

    const float* abase = row_ptr(hi, hj, r0);   // row tiles never straddle the hi/hj boundary

    // Running online-LSE state, replicated (identically) across the 16 lanes of a row group.
    float runM[TM], runS[TM];
#pragma unroll
    for (int i = 0; i < TM; i++) { runM[i] = -CUDART_INF_F; runS[i] = 0.f; }

    for (int c0 = cbeg; c0 < cbeg + CHUNK_COLS; c0 += BN) {
        const float* bbase = row_ptr(hi, hj, c0);

        float acc[TM][TN];
#pragma unroll
        for (int i = 0; i < TM; i++)
#pragma unroll
            for (int j = 0; j < TN; j++) acc[i][j] = 0.f;

        for (int k0 = 0; k0 < DIM; k0 += BK) {
            __syncthreads();
            // Load 128x32 A and B sub-tiles, coalesced float4, transposed store.
#pragma unroll
            for (int q = 0; q < 4; q++) {
                int fi  = tid + NTHREADS * q;        // 0..1023 float4 slots
                int row = fi >> 3;                   // 0..127
                int kq  = (fi & 7) << 2;             // 0,4,...,28
                float4 va = *(const float4*)(abase + (size_t)row * DIM + k0 + kq);
                As[kq + 0][row] = va.x; As[kq + 1][row] = va.y;
                As[kq + 2][row] = va.z; As[kq + 3][row] = va.w;
                float4 vb = *(const float4*)(bbase + (size_t)row * DIM + k0 + kq);
                Bs[kq + 0][row] = vb.x; Bs[kq + 1][row] = vb.y;
                Bs[kq + 2][row] = vb.z; Bs[kq + 3][row] = vb.w;
            }
            __syncthreads();

#pragma unroll
            for (int k = 0; k < BK; k++) {
                float a[TM], b[TN];
                *(float4*)&a[0] = *(const float4*)&As[k][ty * TM];
                *(float4*)&a[4] = *(const float4*)&As[k][ty * TM + 4];
                *(float4*)&b[0] = *(const float4*)&Bs[k][tx * TN];
                *(float4*)&b[4] = *(const float4*)&Bs[k][tx * TN + 4];
#pragma unroll
                for (int i = 0; i < TM; i++)
#pragma unroll
                    for (int j = 0; j < TN; j++)
                        acc[i][j] = fmaf(a[i], b[j], acc[i][j]);
            }
        }

        // ---- Epilogue: scale by 1/temp, mask diagonal, tile-local row max ----
        float tMv[TM], tSv[TM];
#pragma unroll
        for (int i = 0; i < TM; i++) {
            const int gr = r0 + ty * TM + i;
            float m = -CUDART_INF_F;
#pragma unroll
            for (int j = 0; j < TN; j++) {
                const int gc = c0 + tx * TN + j;
                float v = acc[i][j] * SIMSCALE;
                if (gr == gc) v = -CUDART_INF_F;   // self-similarity mask
                acc[i][j] = v;
                m = fmaxf(m, v);
            }
            tMv[i] = m;
        }
        // Reduce max across the 16 lanes covering this row group (lanes 0-15 / 16-31).
#pragma unroll
        for (int off = 8; off > 0; off >>= 1)
#pragma unroll
            for (int i = 0; i < TM; i++)
                tMv[i] = fmaxf(tMv[i], __shfl_xor_sync(0xffffffffu, tMv[i], off));
        // Local sumexp against the (now uniform) tile max, then reduce.
#pragma unroll
        for (int i = 0; i < TM; i++) {
            float s = 0.f;
#pragma unroll
            for (int j = 0; j < TN; j++)
                s += __expf(acc[i][j] - tMv[i]);   // masked entry: exp(-inf) = 0
            tSv[i] = s;
        }
#pragma unroll
        for (int off = 8; off > 0; off >>= 1)
#pragma unroll
            for (int i = 0; i < TM; i++)
                tSv[i] += __shfl_xor_sync(0xffffffffu, tSv[i], off);
        // Online merge into running state.
#pragma unroll
        for (int i = 0; i < TM; i++) {
            const float nm = fmaxf(runM[i], tMv[i]);
            runS[i] = runS[i] * __expf(runM[i] - nm) + tSv[i] * __expf(tMv[i] - nm);
            runM[i] = nm;
        }
    }

    if (tx == 0) {
#pragma unroll
        for (int i = 0; i < TM; i++) {
            const int r = r0 + ty * TM + i;
            g_pm[ch][r] = runM[i];
            g_ps[ch][r] = runS[i];
        }
    }
}

// Merge the NCHUNK partial (m,s) pairs per row, compute pos_i, emit per-row loss.
// One warp per positive pair p: rows p and p+BATCHSZ share pos = dot(h_i[p], h_j[p]) / temp.
__global__ void combine_kernel(const float* __restrict__ hi, const float* __restrict__ hj) {
    const int gwarp = (int)((blockIdx.x * blockDim.x + threadIdx.x) >> 5);
    const int lane  = threadIdx.x & 31;
    if (gwarp >= BATCHSZ) return;

    const float* a = hi + (size_t)gwarp * DIM;
    const float* b = hj + (size_t)gwarp * DIM;
    const int k = lane * 8;
    float4 a0 = *(const float4*)(a + k);
    float4 a1 = *(const float4*)(a + k + 4);
    float4 b0 = *(const float4*)(b + k);
    float4 b1 = *(const float4*)(b + k + 4);
    float d = a0.x*b0.x + a0.y*b0.y + a0.z*b0.z + a0.w*b0.w
            + a1.x*b1.x + a1.y*b1.y + a1.z*b1.z + a1.w*b1.w;
#pragma unroll
    for (int off = 16; off > 0; off >>= 1)
        d += __shfl_xor_sync(0xffffffffu, d, off);
    const float pos = d * SIMSCALE;

    if (lane < 2) {
        const int r = gwarp + lane * BATCHSZ;
        float M = -CUDART_INF_F;
#pragma unroll
        for (int c = 0; c < NCHUNK; c++) M = fmaxf(M, g_pm[c][r]);
        float S = 0.f;
#pragma unroll
        for (int c = 0; c < NCHUNK; c++) S += g_ps[c][r] * __expf(g_pm[c][r] - M);
        g_lrow[r] = M + logf(S) - pos;
    }
}

// Deterministic single-block tree reduction -> mean. (No float atomics: replay-stable.)
__global__ void reduce_kernel(float* __restrict__ out) {
    __shared__ float sm[256];
    const int tid = threadIdx.x;
    float s = 0.f;
    for (int i = tid; i < NROWS; i += 256) s += g_lrow[i];
    sm[tid] = s;
    __syncthreads();
    for (int stride = 128; stride > 0; stride >>= 1) {
        if (tid < stride) sm[tid] += sm[tid + stride];
        __syncthreads();
    }
    if (tid == 0) out[0] = sm[0] * (1.0f / NROWS);
}

extern "C" void kernel_launch(void* const* d_in, const int* in_sizes, int n_in,
                              void* d_out, int out_size) {
    const float* hi = (const float*)d_in[0];
    const float* hj = (const float*)d_in[1];
    float* out = (float*)d_out;

    sim_lse_kernel<<<NROWTILES * NCHUNK, NTHREADS>>>(hi, hj);
    combine_kernel<<<(BATCHSZ * 32) / 256, 256>>>(hi, hj);
    reduce_kernel<<<1, 256>>>(out);
}

// round 3
// speedup vs baseline: 3.5153x; 3.5153x over previous
#include <cuda_runtime.h>
#include <math_constants.h>
#include <cstdint>

// ---------------- problem constants ----------------
#define BATCHSZ 4096
#define DIM     256
#define NROWS   8192
#define SIMSCALE 2.0f          // 1 / temperature
#define NCHUNKS 2              // column halves (h_i | h_j)

// ---------------- device scratch (no allocs allowed) ----------------
__device__ float g_pm[NCHUNKS][NROWS];
__device__ float g_ps[NCHUNKS][NROWS];
__device__ float g_lrow[NROWS];

// ---------------- smem layout (floats) ----------------
#define A_LD   260             // 256 + 4 pad: conflict-free fragment LDS
#define B_LD   36              // 32 + 4 pad
#define AS_OFF 0               // A tile: 128 x A_LD  (tf32 bits)
#define BS_OFF (128 * A_LD)    // 33280: B double buffer, raw f32
#define BS_BUF (128 * B_LD)    // 4608 floats per buffer
#define RED_OFF (BS_OFF + 2 * BS_BUF)   // 42496: [4 wn][128 rows][m,s]
#define SMEM_FLOATS (RED_OFF + 1024)
#define SMEM_BYTES  (SMEM_FLOATS * 4)   // 174080

// ---------------- helpers ----------------
static __device__ __forceinline__ uint32_t f2tf32(float x) {
    uint32_t y;
    asm("cvt.rna.tf32.f32 %0, %1;" : "=r"(y) : "f"(x));   // round-nearest: unbiased
    return y;
}
static __device__ __forceinline__ uint32_t smem_u32(const void* p) {
    uint32_t a;
    asm("{ .reg .u64 t; cvta.to.shared.u64 t, %1; cvt.u32.u64 %0, t; }" : "=r"(a) : "l"(p));
    return a;
}
static __device__ __forceinline__ void mma_tf32(float c[4],
        uint32_t a0, uint32_t a1, uint32_t a2, uint32_t a3,
        uint32_t b0, uint32_t b1) {
    asm volatile(
        "mma.sync.aligned.m16n8k8.row.col.f32.tf32.tf32.f32 "
        "{%0,%1,%2,%3}, {%4,%5,%6,%7}, {%8,%9}, {%0,%1,%2,%3};"
        : "+f"(c[0]), "+f"(c[1]), "+f"(c[2]), "+f"(c[3])
        : "r"(a0), "r"(a1), "r"(a2), "r"(a3), "r"(b0), "r"(b1));
}
#define CP_ASYNC16(dst, src) \
    asm volatile("cp.async.cg.shared.global [%0], [%1], 16;" :: "r"(dst), "l"(src))
#define CP_COMMIT() asm volatile("cp.async.commit_group;" ::: "memory")
#define CP_WAIT0()  asm volatile("cp.async.wait_group 0;"  ::: "memory")

// ==========================================================================
// Fused tf32 mma.sync GEMM + online logsumexp.
// CTA = (row tile rt: 128 rows, A resident in smem) x (column half ch: 4096 cols).
// 8 warps, warp tile 64x32 (warp grid 2m x 4n), m16n8k8 tf32 fragments.
// 256 B-chunks of K=32 streamed via cp.async double buffer; per-128-col-tile
// epilogue folds the sim tile into per-row online (max, sumexp).
// ==========================================================================
__global__ __launch_bounds__(256, 1)
void ntxent_mma_kernel(const float* __restrict__ hi, const float* __restrict__ hj) {
    extern __shared__ float smf[];
    const uint32_t sbase = smem_u32(smf);
    const int tid = threadIdx.x;
    const int w = tid >> 5, lane = tid & 31;
    const int g = lane >> 2, tq = lane & 3;     // quad layout for mma frags
    const int wm = w >> 2, wn = w & 3;          // warp grid 2 x 4

    const int rt = blockIdx.x & 63;
    const int ch = blockIdx.x >> 6;
    const int r0 = rt * 128;
    const float* arow = (rt < 32) ? hi + (size_t)rt * 128 * DIM
                                  : hj + (size_t)(rt - 32) * 128 * DIM;
    const float* bsrc = ch ? hj : hi;

    // -------- prologue: cp.async B chunk 0 -> buf 0 --------
#pragma unroll
    for (int i = 0; i < 4; i++) {
        int f = i * 256 + tid;
        int n = f >> 3, kk = (f & 7) << 2;
        CP_ASYNC16(sbase + (uint32_t)(BS_OFF + n * B_LD + kk) * 4,
                   bsrc + (size_t)n * DIM + kk);
    }
    CP_COMMIT();

    // -------- A tile (128 x 256) -> smem, tf32-rounded, once --------
#pragma unroll
    for (int i = 0; i < 32; i++) {
        int f = i * 256 + tid;
        int r = f >> 6, k = (f & 63) << 2;
        float4 v = *(const float4*)(arow + (size_t)r * DIM + k);
        uint4 wv = { f2tf32(v.x), f2tf32(v.y), f2tf32(v.z), f2tf32(v.w) };
        *(uint4*)(smf + r * A_LD + k) = wv;
    }

    float acc[4][4][4];
#pragma unroll
    for (int mf = 0; mf < 4; mf++)
#pragma unroll
        for (int nf = 0; nf < 4; nf++)
#pragma unroll
            for (int c = 0; c < 4; c++) acc[mf][nf][c] = 0.f;

    float runM = -CUDART_INF_F, runS = 0.f;
    const uint32_t* As = (const uint32_t*)smf;

    for (int gc = 0; gc < 256; gc++) {          // 32 tiles x 8 K-chunks
        CP_WAIT0();
        __syncthreads();                        // chunk gc visible; prev compute done
        const int buf = gc & 1;

        if (gc < 255) {                         // prefetch chunk gc+1 (other buffer)
            const int t1 = (gc + 1) >> 3, kc1 = (gc + 1) & 7;
            const float* src0 = bsrc + (size_t)(t1 * 128) * DIM + kc1 * 32;
            const uint32_t dbase = sbase + (uint32_t)(BS_OFF + ((gc + 1) & 1) * BS_BUF) * 4;
#pragma unroll
            for (int i = 0; i < 4; i++) {
                int f = i * 256 + tid;
                int n = f >> 3, kk = (f & 7) << 2;
                CP_ASYNC16(dbase + (uint32_t)(n * B_LD + kk) * 4,
                           src0 + (size_t)n * DIM + kk);
            }
            CP_COMMIT();
        }

        // -------- MMA: 4 k8-steps on this chunk --------
        const float* Braw = smf + BS_OFF + buf * BS_BUF;
        const int kc = gc & 7;
#pragma unroll
        for (int kq = 0; kq < 4; kq++) {
            const int c0 = kc * 32 + kq * 8 + tq;
            uint32_t bf[4][2];
#pragma unroll
            for (int nf = 0; nf < 4; nf++) {
                const float* bp = Braw + (wn * 32 + nf * 8 + g) * B_LD + kq * 8 + tq;
                bf[nf][0] = f2tf32(bp[0]);
                bf[nf][1] = f2tf32(bp[4]);
            }
#pragma unroll
            for (int mf = 0; mf < 4; mf++) {
                const uint32_t* ap = As + (wm * 64 + mf * 16 + g) * A_LD + c0;
                uint32_t a0 = ap[0], a1 = ap[8 * A_LD], a2 = ap[4], a3 = ap[8 * A_LD + 4];
#pragma unroll
                for (int nf = 0; nf < 4; nf++)
                    mma_tf32(acc[mf][nf], a0, a1, a2, a3, bf[nf][0], bf[nf][1]);
            }
        }

        // -------- epilogue once per 128-col tile --------
        if (kc == 7) {
            const int t = gc >> 3;
            const int c0g = ch * 4096 + t * 128 + wn * 32 + tq * 2;
            float* red = smf + RED_OFF;         // [wn][row][m,s]
            float tm[8], ts[8];
#pragma unroll
            for (int mf = 0; mf < 4; mf++)
#pragma unroll
                for (int hh = 0; hh < 2; hh++) {
                    const int gr = r0 + wm * 64 + mf * 16 + g + hh * 8;
                    float m = -CUDART_INF_F;
#pragma unroll
                    for (int nf = 0; nf < 4; nf++)
#pragma unroll
                        for (int c = 0; c < 2; c++) {
                            float v = acc[mf][nf][hh * 2 + c] * SIMSCALE;
                            if (gr == c0g + nf * 8 + c) v = -CUDART_INF_F;  // self-sim mask
                            acc[mf][nf][hh * 2 + c] = v;
                            m = fmaxf(m, v);
                        }
                    tm[mf * 2 + hh] = m;
                }
#pragma unroll
            for (int s = 0; s < 8; s++) {       // quad reduce (lanes sharing a row)
                tm[s] = fmaxf(tm[s], __shfl_xor_sync(0xffffffffu, tm[s], 1));
                tm[s] = fmaxf(tm[s], __shfl_xor_sync(0xffffffffu, tm[s], 2));
            }
#pragma unroll
            for (int mf = 0; mf < 4; mf++)
#pragma unroll
                for (int hh = 0; hh < 2; hh++) {
                    float sv = 0.f;
#pragma unroll
                    for (int nf = 0; nf < 4; nf++)
#pragma unroll
                        for (int c = 0; c < 2; c++)
                            sv += __expf(acc[mf][nf][hh * 2 + c] - tm[mf * 2 + hh]);
                    ts[mf * 2 + hh] = sv;
                }
#pragma unroll
            for (int s = 0; s < 8; s++) {
                ts[s] += __shfl_xor_sync(0xffffffffu, ts[s], 1);
                ts[s] += __shfl_xor_sync(0xffffffffu, ts[s], 2);
            }
            if (tq == 0) {
#pragma unroll
                for (int mf = 0; mf < 4; mf++)
#pragma unroll
                    for (int hh = 0; hh < 2; hh++) {
                        int row = wm * 64 + mf * 16 + g + hh * 8;
                        red[(wn * 128 + row) * 2 + 0] = tm[mf * 2 + hh];
                        red[(wn * 128 + row) * 2 + 1] = ts[mf * 2 + hh];
                    }
            }
            __syncthreads();
            if (tid < 128) {                     // thread tid owns row r0+tid
                float M = red[tid * 2];
#pragma unroll
                for (int q = 1; q < 4; q++) M = fmaxf(M, red[(q * 128 + tid) * 2]);
                float S = 0.f;
#pragma unroll
                for (int q = 0; q < 4; q++)
                    S += red[(q * 128 + tid) * 2 + 1] * __expf(red[(q * 128 + tid) * 2] - M);
                float nm = fmaxf(runM, M);
                runS = runS * __expf(runM - nm) + S * __expf(M - nm);
                runM = nm;
            }
            __syncthreads();                     // red reads done before next tile writes
#pragma unroll
            for (int mf = 0; mf < 4; mf++)
#pragma unroll
                for (int nf = 0; nf < 4; nf++)
#pragma unroll
                    for (int c = 0; c < 4; c++) acc[mf][nf][c] = 0.f;
        }
    }

    if (tid < 128) {
        g_pm[ch][r0 + tid] = runM;
        g_ps[ch][r0 + tid] = runS;
    }
}

// ==========================================================================
// Merge 2 column-half partials per row, compute pos_i (exact fp32), per-row loss.
// ==========================================================================
__global__ void combine_kernel(const float* __restrict__ hi, const float* __restrict__ hj) {
    const int gwarp = (int)((blockIdx.x * blockDim.x + threadIdx.x) >> 5);
    const int lane = threadIdx.x & 31;
    if (gwarp >= BATCHSZ) return;

    const float* a = hi + (size_t)gwarp * DIM;
    const float* b = hj + (size_t)gwarp * DIM;
    const int k = lane * 8;
    float4 a0 = *(const float4*)(a + k);
    float4 a1 = *(const float4*)(a + k + 4);
    float4 b0 = *(const float4*)(b + k);
    float4 b1 = *(const float4*)(b + k + 4);
    float d = a0.x * b0.x + a0.y * b0.y + a0.z * b0.z + a0.w * b0.w
            + a1.x * b1.x + a1.y * b1.y + a1.z * b1.z + a1.w * b1.w;
#pragma unroll
    for (int off = 16; off > 0; off >>= 1)
        d += __shfl_xor_sync(0xffffffffu, d, off);
    const float pos = d * SIMSCALE;

    if (lane < 2) {
        const int r = gwarp + lane * BATCHSZ;
        float m0 = g_pm[0][r], m1 = g_pm[1][r];
        float M = fmaxf(m0, m1);
        float S = g_ps[0][r] * __expf(m0 - M) + g_ps[1][r] * __expf(m1 - M);
        g_lrow[r] = M + logf(S) - pos;
    }
}

// Deterministic single-block reduction -> mean (replay-stable, no atomics).
__global__ void reduce_kernel(float* __restrict__ out) {
    __shared__ float sm[256];
    const int tid = threadIdx.x;
    float s = 0.f;
    for (int i = tid; i < NROWS; i += 256) s += g_lrow[i];
    sm[tid] = s;
    __syncthreads();
    for (int stride = 128; stride > 0; stride >>= 1) {
        if (tid < stride) sm[tid] += sm[tid + stride];
        __syncthreads();
    }
    if (tid == 0) out[0] = sm[0] * (1.0f / NROWS);
}

extern "C" void kernel_launch(void* const* d_in, const int* in_sizes, int n_in,
                              void* d_out, int out_size) {
    const float* hi = (const float*)d_in[0];
    const float* hj = (const float*)d_in[1];
    float* out = (float*)d_out;

    cudaFuncSetAttribute(ntxent_mma_kernel,
                         cudaFuncAttributeMaxDynamicSharedMemorySize, SMEM_BYTES);
    ntxent_mma_kernel<<<128, 256, SMEM_BYTES>>>(hi, hj);
    combine_kernel<<<(BATCHSZ * 32) / 256, 256>>>(hi, hj);
    reduce_kernel<<<1, 256>>>(out);
}

// round 4
// speedup vs baseline: 3.6569x; 1.0403x over previous
#include <cuda_runtime.h>
#include <math_constants.h>
#include <cstdint>

// ---------------- problem constants ----------------
#define BATCHSZ 4096
#define DIM     256
#define NROWS   8192
#define SIMSCALE 2.0f          // 1 / temperature
#define NCHUNKS 2              // column halves (h_i | h_j)

// ---------------- device scratch (no allocs allowed) ----------------
__device__ float g_pm[NCHUNKS][NROWS];
__device__ float g_ps[NCHUNKS][NROWS];
__device__ float g_lrow[NROWS];

// ---------------- smem layout (floats) ----------------
// A' fragment-major: [t16 0..7][ks 0..31][lane 0..31][4 regs] + 4 pad / (t16,ks)
//   AF(t16,ks,lane,reg) = (t16*32+ks)*132 + lane*4 + reg
// B' fragment-major (per 32-K chunk, double buffered):
//   [nt8 0..15][kq 0..3][lane 0..31][2 regs] + 2 pad / (nt,kq)
//   BF(nt,kq,lane,reg) = (nt*4+kq)*66 + lane*2 + reg
#define A_OFF   0
#define A_FLTS  (8 * 32 * 132)          // 33792
#define B_OFF   A_FLTS
#define B_BUF   (16 * 4 * 66)           // 4224 floats per buffer
#define RED_OFF (B_OFF + 2 * B_BUF)     // 42240: [4 wn][128 rows][m,s]
#define SMEM_FLOATS (RED_OFF + 1024)    // 43264
#define SMEM_BYTES  (SMEM_FLOATS * 4)   // 173056

// ---------------- helpers ----------------
static __device__ __forceinline__ uint32_t f2tf32(float x) {
    uint32_t y;
    asm("cvt.rna.tf32.f32 %0, %1;" : "=r"(y) : "f"(x));   // round-nearest: unbiased
    return y;
}
static __device__ __forceinline__ void mma_tf32(float c[4],
        uint32_t a0, uint32_t a1, uint32_t a2, uint32_t a3,
        uint32_t b0, uint32_t b1) {
    asm volatile(
        "mma.sync.aligned.m16n8k8.row.col.f32.tf32.tf32.f32 "
        "{%0,%1,%2,%3}, {%4,%5,%6,%7}, {%8,%9}, {%0,%1,%2,%3};"
        : "+f"(c[0]), "+f"(c[1]), "+f"(c[2]), "+f"(c[3])
        : "r"(a0), "r"(a1), "r"(a2), "r"(a3), "r"(b0), "r"(b1));
}

// ==========================================================================
// Fused tf32 mma.sync GEMM + online logsumexp, fragment-major smem.
// CTA = (row tile rt: 128 rows, A resident) x (column half ch: 4096 cols).
// 8 warps, warp tile 64x32 (grid 2m x 4n), m16n8k8 tf32.
// 256 K-chunks (32 tiles x 8), B double-buffered via LDG-prefetch + STS.
// ==========================================================================
__global__ __launch_bounds__(256, 1)
void ntxent_mma_kernel(const float* __restrict__ hi, const float* __restrict__ hj) {
    extern __shared__ float smf[];
    uint32_t* smu = (uint32_t*)smf;
    const int tid = threadIdx.x;
    const int w = tid >> 5, lane = tid & 31;
    const int g = lane >> 2, tq = lane & 3;     // quad layout for mma frags
    const int wm = w >> 2, wn = w & 3;          // warp grid 2 x 4

    const int rt = blockIdx.x & 63;
    const int ch = blockIdx.x >> 6;
    const int r0 = rt * 128;
    const float* arow = (rt < 32) ? hi + (size_t)rt * 128 * DIM
                                  : hj + (size_t)(rt - 32) * 128 * DIM;
    const float* bsrc = ch ? hj : hi;

    // Per-chunk B element ownership: 4 float4 per thread.
    // f = i*256+tid -> n = f>>3 (row 0..127), kk = (f&7)*4 (chunk-local k).
    const int pn[4] = { (0 * 256 + tid) >> 3, (1 * 256 + tid) >> 3,
                        (2 * 256 + tid) >> 3, (3 * 256 + tid) >> 3 };
    const int pk = (tid & 7) * 4;               // same for all i since 256%8==0
    // Fragment store offsets (float index, +2*j per element j)
    uint32_t pb[4];
#pragma unroll
    for (int i = 0; i < 4; i++)
        pb[i] = (uint32_t)(((pn[i] >> 3) * 4 + (pk >> 3)) * 66
                           + (pn[i] & 7) * 8 + ((pk >> 2) & 1));

    // -------- prologue: LDG chunk 0 --------
    float4 pf[4];
#pragma unroll
    for (int i = 0; i < 4; i++)
        pf[i] = *(const float4*)(bsrc + (size_t)pn[i] * DIM + pk);

    // -------- A tile -> fragment-major smem (tf32) --------
#pragma unroll
    for (int i = 0; i < 32; i++) {
        int f = i * 256 + tid;
        int r = f >> 6, k = (f & 63) << 2;
        float4 v = *(const float4*)(arow + (size_t)r * DIM + k);
        uint32_t o = (uint32_t)(((r >> 4) * 32 + (k >> 3)) * 132 + (r & 7) * 16
                                + ((r >> 3) & 1) + 2 * ((k >> 2) & 1));
        smu[o + 0]  = f2tf32(v.x);
        smu[o + 4]  = f2tf32(v.y);
        smu[o + 8]  = f2tf32(v.z);
        smu[o + 12] = f2tf32(v.w);
    }

    // -------- STS chunk 0 -> buffer 0 --------
    {
        uint32_t* d = smu + B_OFF;
#pragma unroll
        for (int i = 0; i < 4; i++) {
            d[pb[i] + 0] = f2tf32(pf[i].x);
            d[pb[i] + 2] = f2tf32(pf[i].y);
            d[pb[i] + 4] = f2tf32(pf[i].z);
            d[pb[i] + 6] = f2tf32(pf[i].w);
        }
    }
    __syncthreads();

    float acc[4][4][4];
#pragma unroll
    for (int mf = 0; mf < 4; mf++)
#pragma unroll
        for (int nf = 0; nf < 4; nf++)
#pragma unroll
            for (int c = 0; c < 4; c++) acc[mf][nf][c] = 0.f;

    float runM = -CUDART_INF_F, runS = 0.f;

    for (int t = 0; t < 32; t++) {
        for (int kc = 0; kc < 8; kc++) {
            const int gc = t * 8 + kc;
            const int buf = gc & 1;

            if (gc < 255) {                     // prefetch chunk gc+1 to regs
                const int t1 = (gc + 1) >> 3, kc1 = (gc + 1) & 7;
                const float* base = bsrc + (size_t)(t1 * 128) * DIM + kc1 * 32;
#pragma unroll
                for (int i = 0; i < 4; i++)
                    pf[i] = *(const float4*)(base + (size_t)pn[i] * DIM + pk);
            }

            // -------- MMA: 4 k8-steps, vector fragment loads --------
            const uint32_t* Bu = smu + B_OFF + buf * B_BUF;
#pragma unroll
            for (int kq = 0; kq < 4; kq++) {
                uint2 bfr[4];
#pragma unroll
                for (int nf = 0; nf < 4; nf++)
                    bfr[nf] = *(const uint2*)(Bu + ((wn * 4 + nf) * 4 + kq) * 66
                                              + lane * 2);
#pragma unroll
                for (int mf = 0; mf < 4; mf++) {
                    uint4 af = *(const uint4*)(smu
                        + ((wm * 4 + mf) * 32 + (kc * 4 + kq)) * 132 + lane * 4);
#pragma unroll
                    for (int nf = 0; nf < 4; nf++)
                        mma_tf32(acc[mf][nf], af.x, af.y, af.z, af.w,
                                 bfr[nf].x, bfr[nf].y);
                }
            }

            if (gc < 255) {                     // STS chunk gc+1 -> other buffer
                uint32_t* d = smu + B_OFF + (buf ^ 1) * B_BUF;
#pragma unroll
                for (int i = 0; i < 4; i++) {
                    d[pb[i] + 0] = f2tf32(pf[i].x);
                    d[pb[i] + 2] = f2tf32(pf[i].y);
                    d[pb[i] + 4] = f2tf32(pf[i].z);
                    d[pb[i] + 6] = f2tf32(pf[i].w);
                }
            }
            __syncthreads();
        }

        // -------- epilogue: fold 128-col sim tile into online (m, s) --------
        {
            const int c0g = ch * 4096 + t * 128 + wn * 32 + tq * 2;
            float* red = smf + RED_OFF;         // [wn][row][m,s]
            float tm[8], ts[8];
#pragma unroll
            for (int mf = 0; mf < 4; mf++)
#pragma unroll
                for (int hh = 0; hh < 2; hh++) {
                    const int gr = r0 + wm * 64 + mf * 16 + g + hh * 8;
                    float m = -CUDART_INF_F;
#pragma unroll
                    for (int nf = 0; nf < 4; nf++)
#pragma unroll
                        for (int c = 0; c < 2; c++) {
                            float v = acc[mf][nf][hh * 2 + c] * SIMSCALE;
                            if (gr == c0g + nf * 8 + c) v = -CUDART_INF_F;  // self mask
                            acc[mf][nf][hh * 2 + c] = v;
                            m = fmaxf(m, v);
                        }
                    tm[mf * 2 + hh] = m;
                }
#pragma unroll
            for (int s = 0; s < 8; s++) {       // quad reduce (lanes of same row)
                tm[s] = fmaxf(tm[s], __shfl_xor_sync(0xffffffffu, tm[s], 1));
                tm[s] = fmaxf(tm[s], __shfl_xor_sync(0xffffffffu, tm[s], 2));
            }
#pragma unroll
            for (int mf = 0; mf < 4; mf++)
#pragma unroll
                for (int hh = 0; hh < 2; hh++) {
                    float sv = 0.f;
#pragma unroll
                    for (int nf = 0; nf < 4; nf++)
#pragma unroll
                        for (int c = 0; c < 2; c++)
                            sv += __expf(acc[mf][nf][hh * 2 + c] - tm[mf * 2 + hh]);
                    ts[mf * 2 + hh] = sv;
                }
#pragma unroll
            for (int s = 0; s < 8; s++) {
                ts[s] += __shfl_xor_sync(0xffffffffu, ts[s], 1);
                ts[s] += __shfl_xor_sync(0xffffffffu, ts[s], 2);
            }
            if (tq == 0) {
#pragma unroll
                for (int mf = 0; mf < 4; mf++)
#pragma unroll
                    for (int hh = 0; hh < 2; hh++) {
                        int row = wm * 64 + mf * 16 + g + hh * 8;
                        red[(wn * 128 + row) * 2 + 0] = tm[mf * 2 + hh];
                        red[(wn * 128 + row) * 2 + 1] = ts[mf * 2 + hh];
                    }
            }
            __syncthreads();
            if (tid < 128) {                    // thread tid owns row r0+tid
                float M = red[tid * 2];
#pragma unroll
                for (int q = 1; q < 4; q++) M = fmaxf(M, red[(q * 128 + tid) * 2]);
                float S = 0.f;
#pragma unroll
                for (int q = 0; q < 4; q++)
                    S += red[(q * 128 + tid) * 2 + 1]
                       * __expf(red[(q * 128 + tid) * 2] - M);
                float nm = fmaxf(runM, M);
                runS = runS * __expf(runM - nm) + S * __expf(M - nm);
                runM = nm;
            }
            __syncthreads();                    // red reads done before next tile
#pragma unroll
            for (int mf = 0; mf < 4; mf++)
#pragma unroll
                for (int nf = 0; nf < 4; nf++)
#pragma unroll
                    for (int c = 0; c < 4; c++) acc[mf][nf][c] = 0.f;
        }
    }

    if (tid < 128) {
        g_pm[ch][r0 + tid] = runM;
        g_ps[ch][r0 + tid] = runS;
    }
}

// ==========================================================================
// Merge 2 column-half partials per row, compute pos_i (exact fp32), per-row loss.
// ==========================================================================
__global__ void combine_kernel(const float* __restrict__ hi, const float* __restrict__ hj) {
    const int gwarp = (int)((blockIdx.x * blockDim.x + threadIdx.x) >> 5);
    const int lane = threadIdx.x & 31;
    if (gwarp >= BATCHSZ) return;

    const float* a = hi + (size_t)gwarp * DIM;
    const float* b = hj + (size_t)gwarp * DIM;
    const int k = lane * 8;
    float4 a0 = *(const float4*)(a + k);
    float4 a1 = *(const float4*)(a + k + 4);
    float4 b0 = *(const float4*)(b + k);
    float4 b1 = *(const float4*)(b + k + 4);
    float d = a0.x * b0.x + a0.y * b0.y + a0.z * b0.z + a0.w * b0.w
            + a1.x * b1.x + a1.y * b1.y + a1.z * b1.z + a1.w * b1.w;
#pragma unroll
    for (int off = 16; off > 0; off >>= 1)
        d += __shfl_xor_sync(0xffffffffu, d, off);
    const float pos = d * SIMSCALE;

    if (lane < 2) {
        const int r = gwarp + lane * BATCHSZ;
        float m0 = g_pm[0][r], m1 = g_pm[1][r];
        float M = fmaxf(m0, m1);
        float S = g_ps[0][r] * __expf(m0 - M) + g_ps[1][r] * __expf(m1 - M);
        g_lrow[r] = M + logf(S) - pos;
    }
}

// Deterministic single-block reduction -> mean (replay-stable, no atomics).
__global__ void reduce_kernel(float* __restrict__ out) {
    __shared__ float sm[256];
    const int tid = threadIdx.x;
    float s = 0.f;
    for (int i = tid; i < NROWS; i += 256) s += g_lrow[i];
    sm[tid] = s;
    __syncthreads();
    for (int stride = 128; stride > 0; stride >>= 1) {
        if (tid < stride) sm[tid] += sm[tid + stride];
        __syncthreads();
    }
    if (tid == 0) out[0] = sm[0] * (1.0f / NROWS);
}

extern "C" void kernel_launch(void* const* d_in, const int* in_sizes, int n_in,
                              void* d_out, int out_size) {
    const float* hi = (const float*)d_in[0];
    const float* hj = (const float*)d_in[1];
    float* out = (float*)d_out;

    cudaFuncSetAttribute(ntxent_mma_kernel,
                         cudaFuncAttributeMaxDynamicSharedMemorySize, SMEM_BYTES);
    ntxent_mma_kernel<<<128, 256, SMEM_BYTES>>>(hi, hj);
    combine_kernel<<<(BATCHSZ * 32) / 256, 256>>>(hi, hj);
    reduce_kernel<<<1, 256>>>(out);
}